// round 1
// baseline (speedup 1.0000x reference)
#include <cuda_runtime.h>
#include <cstddef>

#define DIMN   1024
#define HEADS  16
#define HDIM   64
#define BATCH  4
#define SEQ    1024
#define BHN    (BATCH*HEADS)
#define NB     33

#define GM (BATCH*SEQ)
#define GN DIMN
#define GK DIMN

// ---------------- scratch (device globals; no allocation allowed) ----------
__device__ float g_qh[BHN*SEQ*HDIM];
__device__ float g_kh[BHN*SEQ*HDIM];
__device__ float g_vh[BHN*SEQ*HDIM];
__device__ float g_ctx[BATCH*SEQ*DIMN];

// ---------------- SGEMM: C = X @ W^T + bias (M=4096,N=1024,K=1024) ---------
// head_mode=1: write into [b,h,t,d] head layout with scale
// head_mode=0: write plain [M,N]
__global__ __launch_bounds__(256)
void sgemm_kernel(const float* __restrict__ X, const float* __restrict__ W,
                  const float* __restrict__ bias, float* __restrict__ out,
                  float scale, int head_mode)
{
    __shared__ float As[8][128];
    __shared__ float Bs[8][128];
    const int tid = threadIdx.x;
    const int m0 = blockIdx.y * 128;
    const int n0 = blockIdx.x * 128;
    const int lr = tid >> 1;          // 0..127
    const int lc = (tid & 1) * 4;     // 0 or 4
    const int tx = tid & 15;
    const int ty = tid >> 4;

    float acc[8][8];
    #pragma unroll
    for (int i = 0; i < 8; i++)
        #pragma unroll
        for (int j = 0; j < 8; j++) acc[i][j] = 0.f;

    for (int k0 = 0; k0 < GK; k0 += 8) {
        float4 av = *(const float4*)&X[(size_t)(m0 + lr) * GK + k0 + lc];
        float4 bv = *(const float4*)&W[(size_t)(n0 + lr) * GK + k0 + lc];
        __syncthreads();
        As[lc+0][lr] = av.x; As[lc+1][lr] = av.y; As[lc+2][lr] = av.z; As[lc+3][lr] = av.w;
        Bs[lc+0][lr] = bv.x; Bs[lc+1][lr] = bv.y; Bs[lc+2][lr] = bv.z; Bs[lc+3][lr] = bv.w;
        __syncthreads();
        #pragma unroll
        for (int kk = 0; kk < 8; kk++) {
            float a[8], b[8];
            *(float4*)&a[0] = *(float4*)&As[kk][ty*8];
            *(float4*)&a[4] = *(float4*)&As[kk][ty*8+4];
            *(float4*)&b[0] = *(float4*)&Bs[kk][tx*8];
            *(float4*)&b[4] = *(float4*)&Bs[kk][tx*8+4];
            #pragma unroll
            for (int i = 0; i < 8; i++)
                #pragma unroll
                for (int j = 0; j < 8; j++)
                    acc[i][j] += a[i] * b[j];
        }
    }

    #pragma unroll
    for (int i = 0; i < 8; i++) {
        int m  = m0 + ty*8 + i;
        int nb = n0 + tx*8;
        float r[8];
        #pragma unroll
        for (int j = 0; j < 8; j++) r[j] = (acc[i][j] + bias[nb + j]) * scale;
        if (head_mode) {
            int b = m >> 10, t = m & (SEQ - 1);
            int h = nb >> 6, d = nb & 63;            // 8 cols never cross a head
            float* dst = out + ((size_t)((b*HEADS + h)*SEQ + t)) * HDIM + d;
            *(float4*)dst       = *(float4*)&r[0];
            *(float4*)(dst + 4) = *(float4*)&r[4];
        } else {
            float* dst = out + (size_t)m * GN + nb;
            *(float4*)dst       = *(float4*)&r[0];
            *(float4*)(dst + 4) = *(float4*)&r[4];
        }
    }
}

// ---------------- attention kernel ----------------------------------------
#define TQ 32
#define TK 128
#define ESTR 1032      // energy row stride (pad: 1032*4B, q*8 mod 32 -> no conflicts)
#define KSTR 132       // k tile stored transposed: kvT[d][TK], stride 132 (16B aligned)
#define VSTR 68        // v tile row-major: vs[k][HD], stride 68 (16B aligned)
#define KVFLOATS 8704  // max(64*132=8448, 128*68=8704)
#define SMEM_FLOATS (TQ*ESTR + TQ*HDIM + KVFLOATS + NB*128 + TQ*NB + TQ*NB)
#define SMEM_BYTES  (SMEM_FLOATS * 4)   // 200448 B

__global__ __launch_bounds__(256)
void attn_kernel(const float* __restrict__ rpe_w, float* __restrict__ align_out)
{
    extern __shared__ float smem[];
    float* e    = smem;                     // [TQ][ESTR]
    float* qs   = e    + TQ * ESTR;         // [TQ][HDIM]
    float* kv   = qs   + TQ * HDIM;         // shared k/v tile buffer
    float* rw   = kv   + KVFLOATS;          // [NB][128]
    float* proj = rw   + NB * 128;          // [TQ][NB]
    float* srow = proj + TQ * NB;           // [TQ][NB]

    const int bh  = blockIdx.y;
    const int q0  = blockIdx.x * TQ;
    const int tid = threadIdx.x;

    // load rpe table + q tile
    for (int i = tid; i < NB * 128; i += 256) rw[i] = rpe_w[i];
    const float* qbase = g_qh + ((size_t)bh * SEQ + q0) * HDIM;
    for (int i = tid; i < TQ * HDIM; i += 256) qs[i] = qbase[i];
    __syncthreads();

    // proj[q][bucket] = qh[q] . rpe_w[bucket, 0:64]
    for (int i = tid; i < TQ * NB; i += 256) {
        int qi = i / NB, t = i % NB;
        float s = 0.f;
        #pragma unroll
        for (int d = 0; d < HDIM; d++) s += qs[qi*HDIM + d] * rw[t*128 + d];
        proj[i] = s;
    }
    __syncthreads();

    // ---- S = Q K^T + rpe_q lookup, into e (full 1024-wide rows) ----
    const int qg = tid >> 5;   // 0..7  -> 4 q rows each
    const int kg = tid & 31;   // 0..31 -> 4 k cols each
    for (int kt = 0; kt < SEQ; kt += TK) {
        const float* kbase = g_kh + ((size_t)bh * SEQ + kt) * HDIM;
        for (int i = tid * 4; i < TK * HDIM; i += 1024) {
            float4 v = *(const float4*)&kbase[i];
            int r = i / HDIM, c = i % HDIM;       // r = k row, c = d
            kv[(c+0)*KSTR + r] = v.x;
            kv[(c+1)*KSTR + r] = v.y;
            kv[(c+2)*KSTR + r] = v.z;
            kv[(c+3)*KSTR + r] = v.w;
        }
        __syncthreads();

        float acc[4][4];
        #pragma unroll
        for (int i = 0; i < 4; i++)
            #pragma unroll
            for (int j = 0; j < 4; j++) acc[i][j] = 0.f;

        #pragma unroll 8
        for (int d = 0; d < HDIM; d++) {
            float a0 = qs[(qg*4+0)*HDIM + d];
            float a1 = qs[(qg*4+1)*HDIM + d];
            float a2 = qs[(qg*4+2)*HDIM + d];
            float a3 = qs[(qg*4+3)*HDIM + d];
            float4 bv = *(float4*)&kv[d*KSTR + kg*4];
            acc[0][0] += a0*bv.x; acc[0][1] += a0*bv.y; acc[0][2] += a0*bv.z; acc[0][3] += a0*bv.w;
            acc[1][0] += a1*bv.x; acc[1][1] += a1*bv.y; acc[1][2] += a1*bv.z; acc[1][3] += a1*bv.w;
            acc[2][0] += a2*bv.x; acc[2][1] += a2*bv.y; acc[2][2] += a2*bv.z; acc[2][3] += a2*bv.w;
            acc[3][0] += a3*bv.x; acc[3][1] += a3*bv.y; acc[3][2] += a3*bv.z; acc[3][3] += a3*bv.w;
        }

        #pragma unroll
        for (int i = 0; i < 4; i++) {
            int q = qg*4 + i;
            int qglob = q0 + q;
            #pragma unroll
            for (int j = 0; j < 4; j++) {
                int k = kt + kg*4 + j;
                int dd = qglob - k;
                dd = dd < -16 ? -16 : (dd > 16 ? 16 : dd);
                e[q*ESTR + k] = acc[i][j] + proj[q*NB + dd + 16];
            }
        }
        __syncthreads();
    }

    // ---- softmax rows + alignment output + RPE bucket sums ----
    const int warp = tid >> 5, lane = tid & 31;
    for (int q = warp*4; q < warp*4 + 4; q++) {
        int qglob = q0 + q;
        float* row = e + q*ESTR;
        float mx = -1e30f;
        for (int k = lane; k < SEQ; k += 32) mx = fmaxf(mx, row[k]);
        #pragma unroll
        for (int o = 16; o; o >>= 1) mx = fmaxf(mx, __shfl_xor_sync(0xffffffffu, mx, o));
        float sum = 0.f;
        for (int k = lane; k < SEQ; k += 32) {
            float p = __expf(row[k] - mx);
            row[k] = p; sum += p;
        }
        #pragma unroll
        for (int o = 16; o; o >>= 1) sum += __shfl_xor_sync(0xffffffffu, sum, o);
        float inv = 1.f / sum;
        float slo = 0.f, shi = 0.f;
        float* arow = align_out + ((size_t)(bh * SEQ + qglob)) * SEQ;
        for (int k = lane; k < SEQ; k += 32) {
            float p = row[k] * inv;
            row[k] = p;
            arow[k] = p;
            if (k <= qglob - 16) slo += p;
            if (k >= qglob + 16) shi += p;
        }
        #pragma unroll
        for (int o = 16; o; o >>= 1) {
            slo += __shfl_xor_sync(0xffffffffu, slo, o);
            shi += __shfl_xor_sync(0xffffffffu, shi, o);
        }
        if (lane == 0) { srow[q*NB + 32] = slo; srow[q*NB + 0] = shi; }
        if (lane >= 1 && lane <= 31) {           // interior buckets, single element
            int k = qglob + 16 - lane;
            srow[q*NB + lane] = (k >= 0 && k < SEQ) ? row[k] : 0.f;
        }
    }
    __syncthreads();

    // ---- context = P @ V + srow @ rpe_v ----
    const int cq = tid >> 3;   // 0..31 q row
    const int dg = tid & 7;    // 0..7  d group (8 floats)
    float cacc[8];
    #pragma unroll
    for (int i = 0; i < 8; i++) cacc[i] = 0.f;

    for (int kt = 0; kt < SEQ; kt += TK) {
        const float* vbase = g_vh + ((size_t)bh * SEQ + kt) * HDIM;
        for (int i = tid * 4; i < TK * HDIM; i += 1024) {
            float4 v = *(const float4*)&vbase[i];
            int r = i / HDIM, c = i % HDIM;
            *(float4*)&kv[r*VSTR + c] = v;
        }
        __syncthreads();
        #pragma unroll 4
        for (int k = 0; k < TK; k++) {
            float p = e[cq*ESTR + kt + k];
            float4 v0 = *(float4*)&kv[k*VSTR + dg*8];
            float4 v1 = *(float4*)&kv[k*VSTR + dg*8 + 4];
            cacc[0] += p*v0.x; cacc[1] += p*v0.y; cacc[2] += p*v0.z; cacc[3] += p*v0.w;
            cacc[4] += p*v1.x; cacc[5] += p*v1.y; cacc[6] += p*v1.z; cacc[7] += p*v1.w;
        }
        __syncthreads();
    }

    #pragma unroll
    for (int t = 0; t < NB; t++) {
        float s = srow[cq*NB + t];
        const float* rv = &rw[t*128 + 64 + dg*8];
        #pragma unroll
        for (int i = 0; i < 8; i++) cacc[i] += s * rv[i];
    }

    int b = bh / HEADS, h = bh % HEADS;
    float* dst = g_ctx + ((size_t)(b*SEQ + q0 + cq)) * DIMN + h*HDIM + dg*8;
    *(float4*)dst       = make_float4(cacc[0], cacc[1], cacc[2], cacc[3]);
    *(float4*)(dst + 4) = make_float4(cacc[4], cacc[5], cacc[6], cacc[7]);
}

// ---------------- launch ---------------------------------------------------
extern "C" void kernel_launch(void* const* d_in, const int* in_sizes, int n_in,
                              void* d_out, int out_size)
{
    const float* q     = (const float*)d_in[0];
    const float* k     = (const float*)d_in[1];
    const float* v     = (const float*)d_in[2];
    const float* Wq    = (const float*)d_in[3];
    const float* bq    = (const float*)d_in[4];
    const float* Wk    = (const float*)d_in[5];
    const float* bk    = (const float*)d_in[6];
    const float* Wv    = (const float*)d_in[7];
    const float* bv    = (const float*)d_in[8];
    const float* rpe_w = (const float*)d_in[9];
    const float* Wo    = (const float*)d_in[10];
    const float* bo    = (const float*)d_in[11];
    float* outp = (float*)d_out;

    float *qh, *kh, *vh, *ctx;
    cudaGetSymbolAddress((void**)&qh,  g_qh);
    cudaGetSymbolAddress((void**)&kh,  g_kh);
    cudaGetSymbolAddress((void**)&vh,  g_vh);
    cudaGetSymbolAddress((void**)&ctx, g_ctx);

    cudaFuncSetAttribute(attn_kernel, cudaFuncAttributeMaxDynamicSharedMemorySize, SMEM_BYTES);

    dim3 gg(GN/128, GM/128);
    sgemm_kernel<<<gg, 256>>>(q, Wq, bq, qh, 0.125f, 1);   // 1/sqrt(64) baked in
    sgemm_kernel<<<gg, 256>>>(k, Wk, bk, kh, 1.0f, 1);
    sgemm_kernel<<<gg, 256>>>(v, Wv, bv, vh, 1.0f, 1);

    float* align_out = outp + (size_t)BATCH * SEQ * DIMN;
    attn_kernel<<<dim3(SEQ/TQ, BHN), 256, SMEM_BYTES>>>(rpe_w, align_out);

    sgemm_kernel<<<gg, 256>>>(ctx, Wo, bo, outp, 1.0f, 0);
}